// round 3
// baseline (speedup 1.0000x reference)
#include <cuda_runtime.h>
#include <math_constants.h>

#define Bc 8
#define Lc 4096
#define Hc 8
#define Dc 64
#define Sc 45
#define Uc 45
#define BHc (Bc*Hc)
#define NSPLIT 4
#define KSPLIT (Lc/NSPLIT)
#define TK 64
#define NCH 32
#define CHL (Lc/NCH)
#define QT 512                  // q-tile size for K1
#define NT (Lc/QT)              // 8 tiles
#define EPT (QT*Sc)             // entries per tile = 23040
#define K1_SMEM ((QT*Dc + QT*Sc)*4)   // 223,232 bytes

// ---- scratch (__device__ globals; no allocation allowed) ----
__device__ int   g_idx[Lc*Sc];
__device__ int   g_mode64;
__device__ int   g_cnt[NT*Lc];
__device__ int   g_cur[NT*Lc];
__device__ int   g_ofs[NT*(Lc+1)];
__device__ unsigned short g_ent[NT*EPT];
__device__ float g_M[BHc*Lc];
__device__ int   g_top[BHc*Uc];
__device__ float g_pm[BHc*Uc*NSPLIT];
__device__ float g_pl[BHc*Uc*NSPLIT];
__device__ float g_pacc[BHc*Uc*NSPLIT*Dc];
__device__ float g_ps[Bc*NCH*Hc*Dc];

// ============================================================
// K0a: detect int64 vs int32 index buffer (OR of odd u32 words)
// ============================================================
__global__ void k0_detect(const unsigned int* __restrict__ p)
{
    __shared__ unsigned int red[256];
    unsigned int acc = 0;
    for (int j = 1 + 2*threadIdx.x; j < Lc*Sc; j += 512) acc |= p[j];
    red[threadIdx.x] = acc;
    __syncthreads();
    for (int o = 128; o > 0; o >>= 1) {
        if (threadIdx.x < o) red[threadIdx.x] |= red[threadIdx.x + o];
        __syncthreads();
    }
    if (threadIdx.x == 0) g_mode64 = (red[0] == 0u) ? 1 : 0;
}

// zero the per-(tile,k) counters
__global__ void b_zero()
{
    int i = blockIdx.x * 256 + threadIdx.x;
    if (i < NT*Lc) g_cnt[i] = 0;
}

// convert indices to int32 + histogram counts per (tile,k)
__global__ void b_convhist(const void* __restrict__ raw)
{
    int q = blockIdx.x * 256 + threadIdx.x;
    if (q >= Lc) return;
    int tile = q >> 9;
    int m64 = g_mode64;
    for (int s = 0; s < Sc; s++) {
        int v;
        if (m64) v = (int)((const long long*)raw)[q*Sc + s];
        else     v = ((const int*)raw)[q*Sc + s];
        g_idx[q*Sc + s] = v;
        atomicAdd(&g_cnt[tile*Lc + v], 1);
    }
}

// exclusive scan of counts per tile -> absolute offsets (+cursor copy)
__global__ void __launch_bounds__(512) b_scan()
{
    __shared__ int part[512];
    int tile = blockIdx.x, t = threadIdx.x;
    int v[8], pre[8], sum = 0;
    for (int j = 0; j < 8; j++) {
        v[j] = g_cnt[tile*Lc + t*8 + j];
        pre[j] = sum; sum += v[j];
    }
    part[t] = sum;
    __syncthreads();
    for (int off = 1; off < 512; off <<= 1) {
        int x = (t >= off) ? part[t-off] : 0;
        __syncthreads();
        part[t] += x;
        __syncthreads();
    }
    int excl = part[t] - sum;
    int base = tile * EPT;
    for (int j = 0; j < 8; j++) {
        int o = base + excl + pre[j];
        g_ofs[tile*(Lc+1) + t*8 + j] = o;
        g_cur[tile*Lc + t*8 + j] = o;
    }
    if (t == 511) g_ofs[tile*(Lc+1) + Lc] = base + part[511];
}

// fill inverted entries: (qlocal<<6)|s bucketed by (tile,k)
__global__ void b_fill()
{
    int q = blockIdx.x * 256 + threadIdx.x;
    if (q >= Lc) return;
    int tile = q >> 9, ql = q & (QT-1);
    for (int s = 0; s < Sc; s++) {
        int k = g_idx[q*Sc + s];
        int pos = atomicAdd(&g_cur[tile*Lc + k], 1);
        g_ent[pos] = (unsigned short)((ql << 6) | s);
    }
}

// ============================================================
// K1: inverted sampled scoring. Block = (tile, bh).
// Q tile resident in smem; K rows streamed once (warp-per-k, prefetch);
// per-(q,s) dot written to its own slot; s-ordered reduce at end.
// ============================================================
__global__ void __launch_bounds__(512) k1_scores(
    const float* __restrict__ Q, const float* __restrict__ K)
{
    extern __shared__ float sm[];
    float* Qs    = sm;               // [QT][64]
    float* slots = sm + QT*Dc;       // [QT][45]
    int tile = blockIdx.x, bh = blockIdx.y;
    int b = bh >> 3, h = bh & 7;
    int tid = threadIdx.x, lane = tid & 31, wid = tid >> 5;
    int qbase = tile * QT;
    const float4* Q4 = (const float4*)Q;
    const float4* K4 = (const float4*)K;
    float4* Qs4 = (float4*)Qs;

    for (int i = tid; i < QT*16; i += 512) {
        int q = i >> 4, d4 = i & 15;
        Qs4[i] = Q4[(((b*Lc + qbase + q)*Hc + h) << 4) + d4];
    }
    __syncthreads();

    const int obase = tile * (Lc+1);
    int g = lane >> 3, t = lane & 7;
    const unsigned short* __restrict__ ent = g_ent;

    float4 ka, kb, na, nb;
    {
        int rb = (((b*Lc + wid)*Hc + h) << 4);
        ka = K4[rb + t*2]; kb = K4[rb + t*2 + 1];
    }
    for (int k = wid; k < Lc; k += 16) {
        int kn = k + 16;
        if (kn < Lc) {
            int rb = (((b*Lc + kn)*Hc + h) << 4);
            na = K4[rb + t*2]; nb = K4[rb + t*2 + 1];
        }
        int o0 = g_ofs[obase + k], o1 = g_ofs[obase + k + 1];
        for (int e = o0; e < o1; e += 4) {
            int ei = e + g;
            int en = (ei < o1) ? (int)ent[ei] : -1;
            float d = 0.f;
            if (en >= 0) {
                int q = en >> 6;
                float4 qa = Qs4[q*16 + t*2];
                float4 qb = Qs4[q*16 + t*2 + 1];
                d = qa.x*ka.x + qa.y*ka.y + qa.z*ka.z + qa.w*ka.w
                  + qb.x*kb.x + qb.y*kb.y + qb.z*kb.z + qb.w*kb.w;
            }
            d += __shfl_xor_sync(0xffffffffu, d, 1);
            d += __shfl_xor_sync(0xffffffffu, d, 2);
            d += __shfl_xor_sync(0xffffffffu, d, 4);
            if (en >= 0 && t == 0) slots[(en >> 6)*Sc + (en & 63)] = d;
        }
        ka = na; kb = nb;
    }
    __syncthreads();

    // s-ordered reduce (matches reference order), thread per q
    {
        int q = tid;
        float mx = -CUDART_INF_F, sv = 0.f;
        #pragma unroll
        for (int s = 0; s < Sc; s++) {
            float v = slots[q*Sc + s];
            mx = fmaxf(mx, v); sv += v;
        }
        g_M[bh*Lc + qbase + q] = mx - sv * (1.0f/(float)Lc);
    }
}

// ============================================================
// K2: top-45 set per (b,h) via 4-level radix select (exact)
// ============================================================
__global__ void __launch_bounds__(256) k2_topk()
{
    __shared__ unsigned int keys[Lc];
    __shared__ int hist[256];
    __shared__ int sel_bin, sel_rem, cnt;
    int bh = blockIdx.x, tid = threadIdx.x;
    for (int i = tid; i < Lc; i += 256) {
        unsigned int u = __float_as_uint(g_M[bh*Lc + i]);
        keys[i] = (u & 0x80000000u) ? ~u : (u | 0x80000000u);
    }
    if (tid == 0) cnt = 0;
    __syncthreads();
    unsigned int prefix = 0; int need = Uc;
    for (int shift = 24; shift >= 0; shift -= 8) {
        hist[tid] = 0;
        __syncthreads();
        for (int i = tid; i < Lc; i += 256) {
            unsigned int k = keys[i];
            if (shift == 24 || (k >> (shift+8)) == prefix)
                atomicAdd(&hist[(k >> shift) & 255], 1);
        }
        __syncthreads();
        if (tid == 0) {
            int c = 0;
            for (int bn = 255; bn >= 0; bn--) {
                int hcount = hist[bn];
                if (c + hcount >= need) { sel_bin = bn; sel_rem = need - c; break; }
                c += hcount;
            }
        }
        __syncthreads();
        prefix = (prefix << 8) | (unsigned int)sel_bin;
        need = sel_rem;
        __syncthreads();
    }
    // prefix == exact threshold key; count(> prefix) = 45 - need
    for (int i = tid; i < Lc; i += 256) {
        if (keys[i] > prefix) { int p = atomicAdd(&cnt, 1); g_top[bh*Uc + p] = i; }
    }
    __syncthreads();
    for (int i = tid; i < Lc; i += 256) {
        if (keys[i] == prefix) {
            int p = atomicAdd(&cnt, 1);
            if (p < Uc) g_top[bh*Uc + p] = i;
        }
    }
}

// ============================================================
// K3: flash-style attention for the 45 selected queries (split-KV x4)
// ============================================================
__global__ void __launch_bounds__(512) k3_attn(
    const float* __restrict__ Q, const float* __restrict__ K,
    const float* __restrict__ V)
{
    __shared__ float Qs[Uc][Dc];
    __shared__ int   qpos_s[Uc];
    __shared__ float Kt[Dc][TK+1];
    __shared__ float Vt[TK][Dc];
    int split = blockIdx.x, bh = blockIdx.y;
    int b = bh >> 3, h = bh & 7;
    int tid = threadIdx.x, lane = tid & 31, w = tid >> 5;

    if (tid < Uc) qpos_s[tid] = g_top[bh*Uc + tid];
    __syncthreads();
    for (int i = tid; i < Uc*Dc; i += 512) {
        int u = i >> 6, d = i & 63;
        int qp = qpos_s[u];
        Qs[u][d] = Q[(((b*Lc + qp)*Hc + h) << 6) + d] * 0.125f;
    }
    __syncthreads();

    int maxqp = 0;
    for (int u = 0; u < Uc; u++) maxqp = max(maxqp, qpos_s[u]);
    int kb0 = split * KSPLIT;
    int ntiles = 0;
    if (maxqp >= kb0) {
        int nn = (maxqp - kb0) / TK + 1;
        ntiles = nn < (KSPLIT/TK) ? nn : (KSPLIT/TK);
    }

    float m[3], lsum[3], acc0[3], acc1[3];
    #pragma unroll
    for (int j = 0; j < 3; j++) { m[j] = -CUDART_INF_F; lsum[j]=0.f; acc0[j]=0.f; acc1[j]=0.f; }

    for (int tile = 0; tile < ntiles; tile++) {
        int kb = kb0 + tile * TK;
        for (int i = tid; i < TK*Dc; i += 512) {
            int k = i >> 6, d = i & 63;
            int gbase = (((b*Lc + kb + k)*Hc + h) << 6) + d;
            Kt[d][k] = K[gbase];
            Vt[k][d] = V[gbase];
        }
        __syncthreads();
        #pragma unroll
        for (int j = 0; j < 3; j++) {
            int u = w*3 + j;
            if (u >= Uc) continue;
            int qp = qpos_s[u];
            if (qp < kb) continue;
            int nk = min(TK, qp - kb + 1);
            float s0 = 0.f, s1 = 0.f;
            #pragma unroll 8
            for (int d = 0; d < Dc; d++) {
                float qd = Qs[u][d];
                s0 += qd * Kt[d][lane];
                s1 += qd * Kt[d][lane+32];
            }
            if (lane >= nk)      s0 = -CUDART_INF_F;
            if (lane + 32 >= nk) s1 = -CUDART_INF_F;
            float tm = fmaxf(s0, s1);
            #pragma unroll
            for (int o = 16; o > 0; o >>= 1) tm = fmaxf(tm, __shfl_xor_sync(0xffffffffu, tm, o));
            float newm = fmaxf(m[j], tm);
            float p0 = __expf(s0 - newm);
            float p1 = __expf(s1 - newm);
            float ps = p0 + p1;
            #pragma unroll
            for (int o = 16; o > 0; o >>= 1) ps += __shfl_xor_sync(0xffffffffu, ps, o);
            float c = __expf(m[j] - newm);
            lsum[j] = lsum[j]*c + ps;
            m[j] = newm;
            acc0[j] *= c; acc1[j] *= c;
            for (int k = 0; k < nk; k++) {
                float pk = __shfl_sync(0xffffffffu, (k < 32) ? p0 : p1, k & 31);
                acc0[j] += pk * Vt[k][lane];
                acc1[j] += pk * Vt[k][lane+32];
            }
        }
        __syncthreads();
    }

    #pragma unroll
    for (int j = 0; j < 3; j++) {
        int u = w*3 + j;
        if (u >= Uc) continue;
        int base = (bh*Uc + u)*NSPLIT + split;
        if (qpos_s[u] < kb0) {
            if (lane == 0) { g_pm[base] = -CUDART_INF_F; g_pl[base] = 0.f; }
            g_pacc[base*Dc + lane] = 0.f;
            g_pacc[base*Dc + lane + 32] = 0.f;
        } else {
            if (lane == 0) { g_pm[base] = m[j]; g_pl[base] = lsum[j]; }
            g_pacc[base*Dc + lane] = acc0[j];
            g_pacc[base*Dc + lane + 32] = acc1[j];
        }
    }
}

// ============================================================
// K4: chunked cumsum of V over L
// ============================================================
__global__ void __launch_bounds__(512) k4a_partials(const float* __restrict__ V)
{
    int b = blockIdx.x, ch = blockIdx.y, tid = threadIdx.x;
    float s = 0.f;
    int base = (b*Lc + ch*CHL) * (Hc*Dc) + tid;
    for (int l = 0; l < CHL; l++) s += V[base + l*(Hc*Dc)];
    g_ps[(b*NCH + ch)*(Hc*Dc) + tid] = s;
}

__global__ void __launch_bounds__(512) k4b_prefix()
{
    int b = blockIdx.x, tid = threadIdx.x;
    float run = 0.f;
    for (int ch = 0; ch < NCH; ch++) {
        int o = (b*NCH + ch)*(Hc*Dc) + tid;
        float t = g_ps[o]; g_ps[o] = run; run += t;
    }
}

__global__ void __launch_bounds__(512) k4c_cumsum(const float* __restrict__ V,
                                                  float* __restrict__ out)
{
    int b = blockIdx.x, ch = blockIdx.y, tid = threadIdx.x;
    float acc = g_ps[(b*NCH + ch)*(Hc*Dc) + tid];
    int base = (b*Lc + ch*CHL) * (Hc*Dc) + tid;
    for (int l = 0; l < CHL; l++) {
        acc += V[base + l*(Hc*Dc)];
        out[base + l*(Hc*Dc)] = acc;
    }
}

// K5: combine split-KV partials and scatter into output
__global__ void __launch_bounds__(64) k5_combine_scatter(float* __restrict__ out)
{
    int u = blockIdx.x, bh = blockIdx.y, d = threadIdx.x;
    int b = bh >> 3, h = bh & 7;
    int base = (bh*Uc + u)*NSPLIT;
    float pm[NSPLIT], pl[NSPLIT];
    float M = -CUDART_INF_F;
    #pragma unroll
    for (int s = 0; s < NSPLIT; s++) {
        pm[s] = g_pm[base+s]; pl[s] = g_pl[base+s];
        M = fmaxf(M, pm[s]);
    }
    float Ls = 0.f, r = 0.f;
    #pragma unroll
    for (int s = 0; s < NSPLIT; s++) {
        float e = __expf(pm[s] - M);
        Ls += pl[s] * e;
        r  += g_pacc[(base+s)*Dc + d] * e;
    }
    int qp = g_top[bh*Uc + u];
    out[(((b*Lc + qp)*Hc + h) << 6) + d] = r / Ls;
}

// ============================================================
extern "C" void kernel_launch(void* const* d_in, const int* in_sizes, int n_in,
                              void* d_out, int out_size)
{
    const float* Q = (const float*)d_in[0];
    const float* K = (const float*)d_in[1];
    const float* V = (const float*)d_in[2];
    const void*  IDXRAW = d_in[3];
    float* out = (float*)d_out;

    cudaFuncSetAttribute(k1_scores, cudaFuncAttributeMaxDynamicSharedMemorySize, K1_SMEM);

    k0_detect<<<1, 256>>>((const unsigned int*)IDXRAW);
    b_zero<<<(NT*Lc + 255)/256, 256>>>();
    b_convhist<<<(Lc + 255)/256, 256>>>(IDXRAW);
    b_scan<<<NT, 512>>>();
    b_fill<<<(Lc + 255)/256, 256>>>();
    k1_scores<<<dim3(NT, BHc), 512, K1_SMEM>>>(Q, K);
    k2_topk<<<BHc, 256>>>();
    k3_attn<<<dim3(NSPLIT, BHc), 512>>>(Q, K, V);
    k4a_partials<<<dim3(Bc, NCH), Hc*Dc>>>(V);
    k4b_prefix<<<Bc, Hc*Dc>>>();
    k4c_cumsum<<<dim3(Bc, NCH), Hc*Dc>>>(V, out);
    k5_combine_scatter<<<dim3(Uc, BHc), Dc>>>(out);
}

// round 4
// speedup vs baseline: 1.1029x; 1.1029x over previous
#include <cuda_runtime.h>
#include <math_constants.h>

#define Bc 8
#define Lc 4096
#define Hc 8
#define Dc 64
#define Sc 45
#define Uc 45
#define BHc (Bc*Hc)
#define NSPLIT 4
#define KSPLIT (Lc/NSPLIT)
#define TK 64
#define NCH 32
#define CHL (Lc/NCH)
#define QT 512                  // q-tile size for K1
#define NT (Lc/QT)              // 8 tiles
#define EPT (QT*Sc)             // entries per tile = 23040 (divisible by 64)
#define K1_SMEM ((QT*Dc + QT*Sc)*4)   // 223,232 bytes

// ---- scratch (__device__ globals; no allocation allowed) ----
__device__ int   g_idx[Lc*Sc];
__device__ int   g_mode64;
__device__ int   g_cnt[NT*Lc];
__device__ int   g_cur[NT*Lc];
__device__ unsigned int g_pack[NT*EPT];   // (k<<15)|(ql<<6)|s, sorted by k per tile
__device__ float g_M[BHc*Lc];
__device__ int   g_top[BHc*Uc];
__device__ float g_pm[BHc*Uc*NSPLIT];
__device__ float g_pl[BHc*Uc*NSPLIT];
__device__ float g_pacc[BHc*Uc*NSPLIT*Dc];
__device__ float g_ps[Bc*NCH*Hc*Dc];

// ============================================================
// K0a: detect int64 vs int32 index buffer (OR of odd u32 words)
// ============================================================
__global__ void k0_detect(const unsigned int* __restrict__ p)
{
    __shared__ unsigned int red[256];
    unsigned int acc = 0;
    for (int j = 1 + 2*threadIdx.x; j < Lc*Sc; j += 512) acc |= p[j];
    red[threadIdx.x] = acc;
    __syncthreads();
    for (int o = 128; o > 0; o >>= 1) {
        if (threadIdx.x < o) red[threadIdx.x] |= red[threadIdx.x + o];
        __syncthreads();
    }
    if (threadIdx.x == 0) g_mode64 = (red[0] == 0u) ? 1 : 0;
}

__global__ void b_zero()
{
    int i = blockIdx.x * 256 + threadIdx.x;
    if (i < NT*Lc) g_cnt[i] = 0;
}

__global__ void b_convhist(const void* __restrict__ raw)
{
    int q = blockIdx.x * 256 + threadIdx.x;
    if (q >= Lc) return;
    int tile = q >> 9;
    int m64 = g_mode64;
    for (int s = 0; s < Sc; s++) {
        int v;
        if (m64) v = (int)((const long long*)raw)[q*Sc + s];
        else     v = ((const int*)raw)[q*Sc + s];
        g_idx[q*Sc + s] = v;
        atomicAdd(&g_cnt[tile*Lc + v], 1);
    }
}

// exclusive scan of counts per tile -> cursors for fill
__global__ void __launch_bounds__(512) b_scan()
{
    __shared__ int part[512];
    int tile = blockIdx.x, t = threadIdx.x;
    int v[8], pre[8], sum = 0;
    for (int j = 0; j < 8; j++) {
        v[j] = g_cnt[tile*Lc + t*8 + j];
        pre[j] = sum; sum += v[j];
    }
    part[t] = sum;
    __syncthreads();
    for (int off = 1; off < 512; off <<= 1) {
        int x = (t >= off) ? part[t-off] : 0;
        __syncthreads();
        part[t] += x;
        __syncthreads();
    }
    int excl = part[t] - sum;
    int base = tile * EPT;
    for (int j = 0; j < 8; j++)
        g_cur[tile*Lc + t*8 + j] = base + excl + pre[j];
}

// fill flat packed entries sorted by key
__global__ void b_fill()
{
    int q = blockIdx.x * 256 + threadIdx.x;
    if (q >= Lc) return;
    int tile = q >> 9, ql = q & (QT-1);
    for (int s = 0; s < Sc; s++) {
        int k = g_idx[q*Sc + s];
        int pos = atomicAdd(&g_cur[tile*Lc + k], 1);
        g_pack[pos] = ((unsigned int)k << 15) | ((unsigned int)ql << 6) | (unsigned int)s;
    }
}

// ============================================================
// K1: flat inverted sampled scoring. Block = (tile, bh).
// 64 groups of 8 lanes; each group strides the tile's packed
// entry list (key-sorted -> L1-served duplicate K rows).
// Fully independent iterations -> high MLP, no pointer chase.
// ============================================================
__global__ void __launch_bounds__(512) k1_scores(
    const float* __restrict__ Q, const float* __restrict__ K)
{
    extern __shared__ float sm[];
    float4* Qs4  = (float4*)sm;          // [QT][16] float4
    float* slots = sm + QT*Dc;           // [QT][45]
    int tile = blockIdx.x, bh = blockIdx.y;
    int b = bh >> 3, h = bh & 7;
    int tid = threadIdx.x;
    int grp = tid >> 3, t = tid & 7;
    int qbase = tile * QT;
    const float4* Q4 = (const float4*)Q;
    const float4* K4 = (const float4*)K;

    for (int i = tid; i < QT*16; i += 512) {
        int q = i >> 4, d4 = i & 15;
        Qs4[i] = Q4[(((b*Lc + qbase + q)*Hc + h) << 4) + d4];
    }
    __syncthreads();

    const unsigned int* __restrict__ pk = g_pack + tile*EPT;
    const int krowbase = (b*Lc*Hc + h) << 4;   // + k*(Hc<<4)
    const int t2 = t*2;

    #pragma unroll 4
    for (int e = grp; e < EPT; e += 64) {
        unsigned int en = pk[e];
        int k  = (int)(en >> 15);
        int ql = (int)((en >> 6) & 511u);
        int ri = krowbase + k*(Hc<<4) + t2;
        float4 ka = K4[ri], kb = K4[ri+1];
        float4 qa = Qs4[ql*16 + t2], qb = Qs4[ql*16 + t2 + 1];
        float d = qa.x*ka.x + qa.y*ka.y + qa.z*ka.z + qa.w*ka.w
                + qb.x*kb.x + qb.y*kb.y + qb.z*kb.z + qb.w*kb.w;
        d += __shfl_xor_sync(0xffffffffu, d, 1);
        d += __shfl_xor_sync(0xffffffffu, d, 2);
        d += __shfl_xor_sync(0xffffffffu, d, 4);
        if (t == 0) slots[ql*Sc + (en & 63u)] = d;
    }
    __syncthreads();

    // s-ordered reduce (matches reference order), thread per q
    {
        int q = tid;
        float mx = -CUDART_INF_F, sv = 0.f;
        #pragma unroll
        for (int s = 0; s < Sc; s++) {
            float v = slots[q*Sc + s];
            mx = fmaxf(mx, v); sv += v;
        }
        g_M[bh*Lc + qbase + q] = mx - sv * (1.0f/(float)Lc);
    }
}

// ============================================================
// K2: top-45 set per (b,h) via 4-level radix select (exact)
// ============================================================
__global__ void __launch_bounds__(256) k2_topk()
{
    __shared__ unsigned int keys[Lc];
    __shared__ int hist[256];
    __shared__ int sel_bin, sel_rem, cnt;
    int bh = blockIdx.x, tid = threadIdx.x;
    for (int i = tid; i < Lc; i += 256) {
        unsigned int u = __float_as_uint(g_M[bh*Lc + i]);
        keys[i] = (u & 0x80000000u) ? ~u : (u | 0x80000000u);
    }
    if (tid == 0) cnt = 0;
    __syncthreads();
    unsigned int prefix = 0; int need = Uc;
    for (int shift = 24; shift >= 0; shift -= 8) {
        hist[tid] = 0;
        __syncthreads();
        for (int i = tid; i < Lc; i += 256) {
            unsigned int k = keys[i];
            if (shift == 24 || (k >> (shift+8)) == prefix)
                atomicAdd(&hist[(k >> shift) & 255], 1);
        }
        __syncthreads();
        if (tid == 0) {
            int c = 0;
            for (int bn = 255; bn >= 0; bn--) {
                int hcount = hist[bn];
                if (c + hcount >= need) { sel_bin = bn; sel_rem = need - c; break; }
                c += hcount;
            }
        }
        __syncthreads();
        prefix = (prefix << 8) | (unsigned int)sel_bin;
        need = sel_rem;
        __syncthreads();
    }
    for (int i = tid; i < Lc; i += 256) {
        if (keys[i] > prefix) { int p = atomicAdd(&cnt, 1); g_top[bh*Uc + p] = i; }
    }
    __syncthreads();
    for (int i = tid; i < Lc; i += 256) {
        if (keys[i] == prefix) {
            int p = atomicAdd(&cnt, 1);
            if (p < Uc) g_top[bh*Uc + p] = i;
        }
    }
}

// ============================================================
// K3: flash-style attention for the 45 selected queries (split-KV x4)
// ============================================================
__global__ void __launch_bounds__(512) k3_attn(
    const float* __restrict__ Q, const float* __restrict__ K,
    const float* __restrict__ V)
{
    __shared__ float Qs[Uc][Dc];
    __shared__ int   qpos_s[Uc];
    __shared__ float Kt[Dc][TK+1];
    __shared__ float Vt[TK][Dc];
    int split = blockIdx.x, bh = blockIdx.y;
    int b = bh >> 3, h = bh & 7;
    int tid = threadIdx.x, lane = tid & 31, w = tid >> 5;

    if (tid < Uc) qpos_s[tid] = g_top[bh*Uc + tid];
    __syncthreads();
    for (int i = tid; i < Uc*Dc; i += 512) {
        int u = i >> 6, d = i & 63;
        int qp = qpos_s[u];
        Qs[u][d] = Q[(((b*Lc + qp)*Hc + h) << 6) + d] * 0.125f;
    }
    __syncthreads();

    int maxqp = 0;
    for (int u = 0; u < Uc; u++) maxqp = max(maxqp, qpos_s[u]);
    int kb0 = split * KSPLIT;
    int ntiles = 0;
    if (maxqp >= kb0) {
        int nn = (maxqp - kb0) / TK + 1;
        ntiles = nn < (KSPLIT/TK) ? nn : (KSPLIT/TK);
    }

    float m[3], lsum[3], acc0[3], acc1[3];
    #pragma unroll
    for (int j = 0; j < 3; j++) { m[j] = -CUDART_INF_F; lsum[j]=0.f; acc0[j]=0.f; acc1[j]=0.f; }

    for (int tile = 0; tile < ntiles; tile++) {
        int kb = kb0 + tile * TK;
        for (int i = tid; i < TK*Dc; i += 512) {
            int k = i >> 6, d = i & 63;
            int gbase = (((b*Lc + kb + k)*Hc + h) << 6) + d;
            Kt[d][k] = K[gbase];
            Vt[k][d] = V[gbase];
        }
        __syncthreads();
        #pragma unroll
        for (int j = 0; j < 3; j++) {
            int u = w*3 + j;
            if (u >= Uc) continue;
            int qp = qpos_s[u];
            if (qp < kb) continue;
            int nk = min(TK, qp - kb + 1);
            float s0 = 0.f, s1 = 0.f;
            #pragma unroll 8
            for (int d = 0; d < Dc; d++) {
                float qd = Qs[u][d];
                s0 += qd * Kt[d][lane];
                s1 += qd * Kt[d][lane+32];
            }
            if (lane >= nk)      s0 = -CUDART_INF_F;
            if (lane + 32 >= nk) s1 = -CUDART_INF_F;
            float tm = fmaxf(s0, s1);
            #pragma unroll
            for (int o = 16; o > 0; o >>= 1) tm = fmaxf(tm, __shfl_xor_sync(0xffffffffu, tm, o));
            float newm = fmaxf(m[j], tm);
            float p0 = __expf(s0 - newm);
            float p1 = __expf(s1 - newm);
            float ps = p0 + p1;
            #pragma unroll
            for (int o = 16; o > 0; o >>= 1) ps += __shfl_xor_sync(0xffffffffu, ps, o);
            float c = __expf(m[j] - newm);
            lsum[j] = lsum[j]*c + ps;
            m[j] = newm;
            acc0[j] *= c; acc1[j] *= c;
            for (int k = 0; k < nk; k++) {
                float pk = __shfl_sync(0xffffffffu, (k < 32) ? p0 : p1, k & 31);
                acc0[j] += pk * Vt[k][lane];
                acc1[j] += pk * Vt[k][lane+32];
            }
        }
        __syncthreads();
    }

    #pragma unroll
    for (int j = 0; j < 3; j++) {
        int u = w*3 + j;
        if (u >= Uc) continue;
        int base = (bh*Uc + u)*NSPLIT + split;
        if (qpos_s[u] < kb0) {
            if (lane == 0) { g_pm[base] = -CUDART_INF_F; g_pl[base] = 0.f; }
            g_pacc[base*Dc + lane] = 0.f;
            g_pacc[base*Dc + lane + 32] = 0.f;
        } else {
            if (lane == 0) { g_pm[base] = m[j]; g_pl[base] = lsum[j]; }
            g_pacc[base*Dc + lane] = acc0[j];
            g_pacc[base*Dc + lane + 32] = acc1[j];
        }
    }
}

// ============================================================
// K4: chunked cumsum of V over L
// ============================================================
__global__ void __launch_bounds__(512) k4a_partials(const float* __restrict__ V)
{
    int b = blockIdx.x, ch = blockIdx.y, tid = threadIdx.x;
    float s = 0.f;
    int base = (b*Lc + ch*CHL) * (Hc*Dc) + tid;
    for (int l = 0; l < CHL; l++) s += V[base + l*(Hc*Dc)];
    g_ps[(b*NCH + ch)*(Hc*Dc) + tid] = s;
}

__global__ void __launch_bounds__(512) k4b_prefix()
{
    int b = blockIdx.x, tid = threadIdx.x;
    float run = 0.f;
    for (int ch = 0; ch < NCH; ch++) {
        int o = (b*NCH + ch)*(Hc*Dc) + tid;
        float t = g_ps[o]; g_ps[o] = run; run += t;
    }
}

__global__ void __launch_bounds__(512) k4c_cumsum(const float* __restrict__ V,
                                                  float* __restrict__ out)
{
    int b = blockIdx.x, ch = blockIdx.y, tid = threadIdx.x;
    float acc = g_ps[(b*NCH + ch)*(Hc*Dc) + tid];
    int base = (b*Lc + ch*CHL) * (Hc*Dc) + tid;
    for (int l = 0; l < CHL; l++) {
        acc += V[base + l*(Hc*Dc)];
        out[base + l*(Hc*Dc)] = acc;
    }
}

// K5: combine split-KV partials and scatter into output
__global__ void __launch_bounds__(64) k5_combine_scatter(float* __restrict__ out)
{
    int u = blockIdx.x, bh = blockIdx.y, d = threadIdx.x;
    int b = bh >> 3, h = bh & 7;
    int base = (bh*Uc + u)*NSPLIT;
    float pm[NSPLIT], pl[NSPLIT];
    float M = -CUDART_INF_F;
    #pragma unroll
    for (int s = 0; s < NSPLIT; s++) {
        pm[s] = g_pm[base+s]; pl[s] = g_pl[base+s];
        M = fmaxf(M, pm[s]);
    }
    float Ls = 0.f, r = 0.f;
    #pragma unroll
    for (int s = 0; s < NSPLIT; s++) {
        float e = __expf(pm[s] - M);
        Ls += pl[s] * e;
        r  += g_pacc[(base+s)*Dc + d] * e;
    }
    int qp = g_top[bh*Uc + u];
    out[(((b*Lc + qp)*Hc + h) << 6) + d] = r / Ls;
}

// ============================================================
extern "C" void kernel_launch(void* const* d_in, const int* in_sizes, int n_in,
                              void* d_out, int out_size)
{
    const float* Q = (const float*)d_in[0];
    const float* K = (const float*)d_in[1];
    const float* V = (const float*)d_in[2];
    const void*  IDXRAW = d_in[3];
    float* out = (float*)d_out;

    cudaFuncSetAttribute(k1_scores, cudaFuncAttributeMaxDynamicSharedMemorySize, K1_SMEM);

    k0_detect<<<1, 256>>>((const unsigned int*)IDXRAW);
    b_zero<<<(NT*Lc + 255)/256, 256>>>();
    b_convhist<<<(Lc + 255)/256, 256>>>(IDXRAW);
    b_scan<<<NT, 512>>>();
    b_fill<<<(Lc + 255)/256, 256>>>();
    k1_scores<<<dim3(NT, BHc), 512, K1_SMEM>>>(Q, K);
    k2_topk<<<BHc, 256>>>();
    k3_attn<<<dim3(NSPLIT, BHc), 512>>>(Q, K, V);
    k4a_partials<<<dim3(Bc, NCH), Hc*Dc>>>(V);
    k4b_prefix<<<Bc, Hc*Dc>>>();
    k4c_cumsum<<<dim3(Bc, NCH), Hc*Dc>>>(V, out);
    k5_combine_scatter<<<dim3(Uc, BHc), Dc>>>(out);
}

// round 5
// speedup vs baseline: 1.4408x; 1.3063x over previous
#include <cuda_runtime.h>
#include <math_constants.h>

#define Bc 8
#define Lc 4096
#define Hc 8
#define Dc 64
#define Sc 45
#define Uc 45
#define BHc (Bc*Hc)
#define NSPLIT 4
#define KSPLIT (Lc/NSPLIT)
#define TK 64
#define NCH 32
#define CHL (Lc/NCH)
#define QT 256                  // q-tile size for K1
#define NT (Lc/QT)              // 16 tiles
#define EPT (QT*Sc)             // 11520 entries per tile (11520/64 = 180 per group)
#define EPG (EPT/64)            // 180
#define K1_SMEM ((QT*Dc + QT*Sc)*4)   // 65536 + 46080 = 111,616 B -> 2 blocks/SM

// ---- scratch (__device__ globals; no allocation allowed) ----
__device__ int   g_idx[Lc*Sc];
__device__ int   g_mode64;
__device__ int   g_cnt[NT*Lc];
__device__ int   g_cur[NT*Lc];
__device__ unsigned int g_pack[NT*EPT];   // (k<<14)|(ql<<6)|s, key-sorted per tile
__device__ float g_M[BHc*Lc];
__device__ int   g_top[BHc*Uc];
__device__ float g_pm[BHc*Uc*NSPLIT];
__device__ float g_pl[BHc*Uc*NSPLIT];
__device__ float g_pacc[BHc*Uc*NSPLIT*Dc];
__device__ float g_ps[Bc*NCH*Hc*Dc];

// ============================================================
// K0a: detect int64 vs int32 index buffer (OR of odd u32 words)
// ============================================================
__global__ void k0_detect(const unsigned int* __restrict__ p)
{
    __shared__ unsigned int red[256];
    unsigned int acc = 0;
    for (int j = 1 + 2*threadIdx.x; j < Lc*Sc; j += 512) acc |= p[j];
    red[threadIdx.x] = acc;
    __syncthreads();
    for (int o = 128; o > 0; o >>= 1) {
        if (threadIdx.x < o) red[threadIdx.x] |= red[threadIdx.x + o];
        __syncthreads();
    }
    if (threadIdx.x == 0) g_mode64 = (red[0] == 0u) ? 1 : 0;
}

__global__ void b_zero()
{
    int i = blockIdx.x * 256 + threadIdx.x;
    if (i < NT*Lc) g_cnt[i] = 0;
}

__global__ void b_convhist(const void* __restrict__ raw)
{
    int q = blockIdx.x * 256 + threadIdx.x;
    if (q >= Lc) return;
    int tile = q / QT;
    int m64 = g_mode64;
    for (int s = 0; s < Sc; s++) {
        int v;
        if (m64) v = (int)((const long long*)raw)[q*Sc + s];
        else     v = ((const int*)raw)[q*Sc + s];
        g_idx[q*Sc + s] = v;
        atomicAdd(&g_cnt[tile*Lc + v], 1);
    }
}

// exclusive scan of counts per tile -> cursors for fill
__global__ void __launch_bounds__(512) b_scan()
{
    __shared__ int part[512];
    int tile = blockIdx.x, t = threadIdx.x;
    int v[8], pre[8], sum = 0;
    for (int j = 0; j < 8; j++) {
        v[j] = g_cnt[tile*Lc + t*8 + j];
        pre[j] = sum; sum += v[j];
    }
    part[t] = sum;
    __syncthreads();
    for (int off = 1; off < 512; off <<= 1) {
        int x = (t >= off) ? part[t-off] : 0;
        __syncthreads();
        part[t] += x;
        __syncthreads();
    }
    int excl = part[t] - sum;
    int base = tile * EPT;
    for (int j = 0; j < 8; j++)
        g_cur[tile*Lc + t*8 + j] = base + excl + pre[j];
}

// fill flat packed entries sorted by key
__global__ void b_fill()
{
    int q = blockIdx.x * 256 + threadIdx.x;
    if (q >= Lc) return;
    int tile = q / QT, ql = q & (QT-1);
    for (int s = 0; s < Sc; s++) {
        int k = g_idx[q*Sc + s];
        int pos = atomicAdd(&g_cur[tile*Lc + k], 1);
        g_pack[pos] = ((unsigned int)k << 14) | ((unsigned int)ql << 6) | (unsigned int)s;
    }
}

// ============================================================
// K1: inverted sampled scoring, contiguous runs + register K reuse.
// Block = (tile, bh). 64 groups of 8 lanes; group g owns entries
// [g*180, (g+1)*180) of the key-sorted list. Duplicate keys within
// a run reuse the register-resident K row (predicated reload).
// ============================================================
__global__ void __launch_bounds__(512) k1_scores(
    const float* __restrict__ Q, const float* __restrict__ K)
{
    extern __shared__ float sm[];
    float4* Qs4  = (float4*)sm;          // [QT][16] float4 (64KB)
    float* slots = sm + QT*Dc;           // [QT][45]
    int tile = blockIdx.x, bh = blockIdx.y;
    int b = bh >> 3, h = bh & 7;
    int tid = threadIdx.x;
    int grp = tid >> 3, t = tid & 7;
    int qbase = tile * QT;
    const float4* Q4 = (const float4*)Q;
    const float4* K4 = (const float4*)K;

    for (int i = tid; i < QT*16; i += 512) {
        int q = i >> 4, d4 = i & 15;
        Qs4[i] = Q4[(((b*Lc + qbase + q)*Hc + h) << 4) + d4];
    }
    __syncthreads();

    const unsigned int* __restrict__ pk = g_pack + tile*EPT + grp*EPG;
    const int krowbase = ((b*Lc*Hc + h) << 4) + t*2;   // + (k<<7)
    const int t2 = t*2;

    int kcur = -1;
    float4 ka, kb;
    for (int e = 0; e < EPG; e++) {
        unsigned int en = pk[e];
        int k = (int)(en >> 14);
        if (k != kcur) {
            int ri = krowbase + (k << 7);
            ka = K4[ri]; kb = K4[ri + 1];
            kcur = k;
        }
        int ql = (int)((en >> 6) & 255u);
        float4 qa = Qs4[ql*16 + t2], qb = Qs4[ql*16 + t2 + 1];
        float d = qa.x*ka.x + qa.y*ka.y + qa.z*ka.z + qa.w*ka.w
                + qb.x*kb.x + qb.y*kb.y + qb.z*kb.z + qb.w*kb.w;
        d += __shfl_xor_sync(0xffffffffu, d, 1);
        d += __shfl_xor_sync(0xffffffffu, d, 2);
        d += __shfl_xor_sync(0xffffffffu, d, 4);
        if (t == 0) slots[ql*Sc + (en & 63u)] = d;
    }
    __syncthreads();

    // s-ordered reduce (matches reference order), thread per q
    if (tid < QT) {
        int q = tid;
        float mx = -CUDART_INF_F, sv = 0.f;
        #pragma unroll
        for (int s = 0; s < Sc; s++) {
            float v = slots[q*Sc + s];
            mx = fmaxf(mx, v); sv += v;
        }
        g_M[bh*Lc + qbase + q] = mx - sv * (1.0f/(float)Lc);
    }
}

// ============================================================
// K2: top-45 set per (b,h) via 4-level radix select (exact)
// ============================================================
__global__ void __launch_bounds__(256) k2_topk()
{
    __shared__ unsigned int keys[Lc];
    __shared__ int hist[256];
    __shared__ int sel_bin, sel_rem, cnt;
    int bh = blockIdx.x, tid = threadIdx.x;
    for (int i = tid; i < Lc; i += 256) {
        unsigned int u = __float_as_uint(g_M[bh*Lc + i]);
        keys[i] = (u & 0x80000000u) ? ~u : (u | 0x80000000u);
    }
    if (tid == 0) cnt = 0;
    __syncthreads();
    unsigned int prefix = 0; int need = Uc;
    for (int shift = 24; shift >= 0; shift -= 8) {
        hist[tid] = 0;
        __syncthreads();
        for (int i = tid; i < Lc; i += 256) {
            unsigned int k = keys[i];
            if (shift == 24 || (k >> (shift+8)) == prefix)
                atomicAdd(&hist[(k >> shift) & 255], 1);
        }
        __syncthreads();
        if (tid == 0) {
            int c = 0;
            for (int bn = 255; bn >= 0; bn--) {
                int hcount = hist[bn];
                if (c + hcount >= need) { sel_bin = bn; sel_rem = need - c; break; }
                c += hcount;
            }
        }
        __syncthreads();
        prefix = (prefix << 8) | (unsigned int)sel_bin;
        need = sel_rem;
        __syncthreads();
    }
    for (int i = tid; i < Lc; i += 256) {
        if (keys[i] > prefix) { int p = atomicAdd(&cnt, 1); g_top[bh*Uc + p] = i; }
    }
    __syncthreads();
    for (int i = tid; i < Lc; i += 256) {
        if (keys[i] == prefix) {
            int p = atomicAdd(&cnt, 1);
            if (p < Uc) g_top[bh*Uc + p] = i;
        }
    }
}

// ============================================================
// K3: flash-style attention for the 45 selected queries (split-KV x4)
// ============================================================
__global__ void __launch_bounds__(512) k3_attn(
    const float* __restrict__ Q, const float* __restrict__ K,
    const float* __restrict__ V)
{
    __shared__ float Qs[Uc][Dc];
    __shared__ int   qpos_s[Uc];
    __shared__ float Kt[Dc][TK+1];
    __shared__ float Vt[TK][Dc];
    int split = blockIdx.x, bh = blockIdx.y;
    int b = bh >> 3, h = bh & 7;
    int tid = threadIdx.x, lane = tid & 31, w = tid >> 5;

    if (tid < Uc) qpos_s[tid] = g_top[bh*Uc + tid];
    __syncthreads();
    for (int i = tid; i < Uc*Dc; i += 512) {
        int u = i >> 6, d = i & 63;
        int qp = qpos_s[u];
        Qs[u][d] = Q[(((b*Lc + qp)*Hc + h) << 6) + d] * 0.125f;
    }
    __syncthreads();

    int maxqp = 0;
    for (int u = 0; u < Uc; u++) maxqp = max(maxqp, qpos_s[u]);
    int kb0 = split * KSPLIT;
    int ntiles = 0;
    if (maxqp >= kb0) {
        int nn = (maxqp - kb0) / TK + 1;
        ntiles = nn < (KSPLIT/TK) ? nn : (KSPLIT/TK);
    }

    float m[3], lsum[3], acc0[3], acc1[3];
    #pragma unroll
    for (int j = 0; j < 3; j++) { m[j] = -CUDART_INF_F; lsum[j]=0.f; acc0[j]=0.f; acc1[j]=0.f; }

    for (int tile = 0; tile < ntiles; tile++) {
        int kb = kb0 + tile * TK;
        for (int i = tid; i < TK*Dc; i += 512) {
            int k = i >> 6, d = i & 63;
            int gbase = (((b*Lc + kb + k)*Hc + h) << 6) + d;
            Kt[d][k] = K[gbase];
            Vt[k][d] = V[gbase];
        }
        __syncthreads();
        #pragma unroll
        for (int j = 0; j < 3; j++) {
            int u = w*3 + j;
            if (u >= Uc) continue;
            int qp = qpos_s[u];
            if (qp < kb) continue;
            int nk = min(TK, qp - kb + 1);
            float s0 = 0.f, s1 = 0.f;
            #pragma unroll 8
            for (int d = 0; d < Dc; d++) {
                float qd = Qs[u][d];
                s0 += qd * Kt[d][lane];
                s1 += qd * Kt[d][lane+32];
            }
            if (lane >= nk)      s0 = -CUDART_INF_F;
            if (lane + 32 >= nk) s1 = -CUDART_INF_F;
            float tm = fmaxf(s0, s1);
            #pragma unroll
            for (int o = 16; o > 0; o >>= 1) tm = fmaxf(tm, __shfl_xor_sync(0xffffffffu, tm, o));
            float newm = fmaxf(m[j], tm);
            float p0 = __expf(s0 - newm);
            float p1 = __expf(s1 - newm);
            float ps = p0 + p1;
            #pragma unroll
            for (int o = 16; o > 0; o >>= 1) ps += __shfl_xor_sync(0xffffffffu, ps, o);
            float c = __expf(m[j] - newm);
            lsum[j] = lsum[j]*c + ps;
            m[j] = newm;
            acc0[j] *= c; acc1[j] *= c;
            for (int k = 0; k < nk; k++) {
                float pk = __shfl_sync(0xffffffffu, (k < 32) ? p0 : p1, k & 31);
                acc0[j] += pk * Vt[k][lane];
                acc1[j] += pk * Vt[k][lane+32];
            }
        }
        __syncthreads();
    }

    #pragma unroll
    for (int j = 0; j < 3; j++) {
        int u = w*3 + j;
        if (u >= Uc) continue;
        int base = (bh*Uc + u)*NSPLIT + split;
        if (qpos_s[u] < kb0) {
            if (lane == 0) { g_pm[base] = -CUDART_INF_F; g_pl[base] = 0.f; }
            g_pacc[base*Dc + lane] = 0.f;
            g_pacc[base*Dc + lane + 32] = 0.f;
        } else {
            if (lane == 0) { g_pm[base] = m[j]; g_pl[base] = lsum[j]; }
            g_pacc[base*Dc + lane] = acc0[j];
            g_pacc[base*Dc + lane + 32] = acc1[j];
        }
    }
}

// ============================================================
// K4: chunked cumsum of V over L
// ============================================================
__global__ void __launch_bounds__(512) k4a_partials(const float* __restrict__ V)
{
    int b = blockIdx.x, ch = blockIdx.y, tid = threadIdx.x;
    float s = 0.f;
    int base = (b*Lc + ch*CHL) * (Hc*Dc) + tid;
    for (int l = 0; l < CHL; l++) s += V[base + l*(Hc*Dc)];
    g_ps[(b*NCH + ch)*(Hc*Dc) + tid] = s;
}

__global__ void __launch_bounds__(512) k4b_prefix()
{
    int b = blockIdx.x, tid = threadIdx.x;
    float run = 0.f;
    for (int ch = 0; ch < NCH; ch++) {
        int o = (b*NCH + ch)*(Hc*Dc) + tid;
        float t = g_ps[o]; g_ps[o] = run; run += t;
    }
}

__global__ void __launch_bounds__(512) k4c_cumsum(const float* __restrict__ V,
                                                  float* __restrict__ out)
{
    int b = blockIdx.x, ch = blockIdx.y, tid = threadIdx.x;
    float acc = g_ps[(b*NCH + ch)*(Hc*Dc) + tid];
    int base = (b*Lc + ch*CHL) * (Hc*Dc) + tid;
    for (int l = 0; l < CHL; l++) {
        acc += V[base + l*(Hc*Dc)];
        out[base + l*(Hc*Dc)] = acc;
    }
}

// K5: combine split-KV partials and scatter into output
__global__ void __launch_bounds__(64) k5_combine_scatter(float* __restrict__ out)
{
    int u = blockIdx.x, bh = blockIdx.y, d = threadIdx.x;
    int b = bh >> 3, h = bh & 7;
    int base = (bh*Uc + u)*NSPLIT;
    float pm[NSPLIT], pl[NSPLIT];
    float M = -CUDART_INF_F;
    #pragma unroll
    for (int s = 0; s < NSPLIT; s++) {
        pm[s] = g_pm[base+s]; pl[s] = g_pl[base+s];
        M = fmaxf(M, pm[s]);
    }
    float Ls = 0.f, r = 0.f;
    #pragma unroll
    for (int s = 0; s < NSPLIT; s++) {
        float e = __expf(pm[s] - M);
        Ls += pl[s] * e;
        r  += g_pacc[(base+s)*Dc + d] * e;
    }
    int qp = g_top[bh*Uc + u];
    out[(((b*Lc + qp)*Hc + h) << 6) + d] = r / Ls;
}

// ============================================================
extern "C" void kernel_launch(void* const* d_in, const int* in_sizes, int n_in,
                              void* d_out, int out_size)
{
    const float* Q = (const float*)d_in[0];
    const float* K = (const float*)d_in[1];
    const float* V = (const float*)d_in[2];
    const void*  IDXRAW = d_in[3];
    float* out = (float*)d_out;

    cudaFuncSetAttribute(k1_scores, cudaFuncAttributeMaxDynamicSharedMemorySize, K1_SMEM);

    k0_detect<<<1, 256>>>((const unsigned int*)IDXRAW);
    b_zero<<<(NT*Lc + 255)/256, 256>>>();
    b_convhist<<<(Lc + 255)/256, 256>>>(IDXRAW);
    b_scan<<<NT, 512>>>();
    b_fill<<<(Lc + 255)/256, 256>>>();
    k1_scores<<<dim3(NT, BHc), 512, K1_SMEM>>>(Q, K);
    k2_topk<<<BHc, 256>>>();
    k3_attn<<<dim3(NSPLIT, BHc), 512>>>(Q, K, V);
    k4a_partials<<<dim3(Bc, NCH), Hc*Dc>>>(V);
    k4b_prefix<<<Bc, Hc*Dc>>>();
    k4c_cumsum<<<dim3(Bc, NCH), Hc*Dc>>>(V, out);
    k5_combine_scatter<<<dim3(Uc, BHc), Dc>>>(out);
}